// round 10
// baseline (speedup 1.0000x reference)
#include <cuda_runtime.h>
#include <cuda_bf16.h>
#include <math.h>
#include <stdint.h>

#define BROWS  4096
#define HDIM   1024
#define FFNDIM 4096
#define DIN    784
#define DOUT   1000
#define NSTEPS 30
#define LN_EPS 1e-5f

typedef __nv_bfloat16 bf16;

// ---------------- scratch ---------------------------------------------------
__device__ __align__(256) float g_xemb[(size_t)BROWS * HDIM];
__device__ __align__(256) float g_h   [(size_t)BROWS * HDIM];
__device__ __align__(256) bf16  g_hn_hi [(size_t)BROWS * HDIM];
__device__ __align__(256) bf16  g_hn_lo [(size_t)BROWS * HDIM];
__device__ __align__(256) bf16  g_hid_hi[(size_t)BROWS * FFNDIM];
__device__ __align__(256) bf16  g_hid_lo[(size_t)BROWS * FFNDIM];
__device__ __align__(256) bf16  g_w1_hi[(size_t)FFNDIM * HDIM];
__device__ __align__(256) bf16  g_w1_lo[(size_t)FFNDIM * HDIM];
__device__ __align__(256) bf16  g_w2_hi[(size_t)HDIM * FFNDIM];
__device__ __align__(256) bf16  g_w2_lo[(size_t)HDIM * FFNDIM];

// ---------------- helpers ---------------------------------------------------
__device__ __forceinline__ uint32_t smem_u32(const void* p) {
    uint32_t a;
    asm("{ .reg .u64 t; cvta.to.shared.u64 t, %1; cvt.u32.u64 %0, t; }" : "=r"(a) : "l"(p));
    return a;
}
static __device__ __forceinline__ uint32_t swz128(uint32_t off) {
    return off ^ ((off >> 3) & 0x70u);
}
__device__ __forceinline__ uint32_t bf2u(bf16 a, bf16 b) {
    unsigned short ua = *reinterpret_cast<unsigned short*>(&a);
    unsigned short ub = *reinterpret_cast<unsigned short*>(&b);
    return (uint32_t)ua | ((uint32_t)ub << 16);
}

#define CP_ASYNC16(saddr, gptr) \
    asm volatile("cp.async.cg.shared.global [%0], [%1], 16;" :: "r"(saddr), "l"(gptr) : "memory")
#define CP_COMMIT() asm volatile("cp.async.commit_group;" ::: "memory")
#define CP_WAIT2()  asm volatile("cp.async.wait_group 2;" ::: "memory")

#define LDSM_X4(r0, r1, r2, r3, addr) \
    asm volatile("ldmatrix.sync.aligned.m8n8.x4.shared.b16 {%0,%1,%2,%3}, [%4];" \
        : "=r"(r0), "=r"(r1), "=r"(r2), "=r"(r3) : "r"(addr))

#define MMA_BF16(d, a, b0, b1) \
    asm volatile("mma.sync.aligned.m16n8k16.row.col.f32.bf16.bf16.f32 " \
        "{%0,%1,%2,%3}, {%4,%5,%6,%7}, {%8,%9}, {%0,%1,%2,%3};" \
        : "+f"((d)[0]), "+f"((d)[1]), "+f"((d)[2]), "+f"((d)[3]) \
        : "r"((a)[0]), "r"((a)[1]), "r"((a)[2]), "r"((a)[3]), "r"(b0), "r"(b1))

// ---------------- split-bf16 HMMA GEMM --------------------------------------
// D[M,N] = A[M,K] @ B[N,K]^T, A = Ah+Al, B = Bh+Bl (K-concat, 3 phases).
// CTA 256(M) x 128(N), 512 threads = 16 warps (4m x 4n), warp tile 64x32.
// BK=64, 4-stage cp.async, single __syncthreads per chunk (CUTLASS multistage),
// B-fragment double buffering.
#define TCG_EPI_TANH 0
#define TCG_EPI_STEP 1

#define NSTG 4
#define STAGE_A_BYTES 32768            // 256 rows x 128B
#define STAGE_B_BYTES 16384            // 128 rows x 128B
#define STAGE_BYTES   (STAGE_A_BYTES + STAGE_B_BYTES)
#define SMEM_MMA (NSTG * STAGE_BYTES)  // 192 KB

template <int KTOT, int NTOT, int EPI>
__global__ __launch_bounds__(512, 1)
void hmma_gemm(const bf16* __restrict__ Ah, const bf16* __restrict__ Al,
               const bf16* __restrict__ Bh, const bf16* __restrict__ Bl,
               const float* __restrict__ bias,
               bf16*  __restrict__ outHi, bf16* __restrict__ outLo,
               float* __restrict__ outF,
               const float* __restrict__ h_old, const float* __restrict__ xemb)
{
    constexpr int KCH = KTOT / 64;
    constexpr int KC_TOTAL = 3 * KCH;

    extern __shared__ __align__(1024) char smem[];
    const uint32_t sb = smem_u32(smem);

    const int tid  = threadIdx.x;
    const int wid  = tid >> 5;
    const int lane = tid & 31;
    const int m0 = blockIdx.y * 256;
    const int n0 = blockIdx.x * 128;
    const int wm = (wid >> 2) * 64;    // 0..192
    const int wn = (wid & 3) * 32;     // 0..96

    float acc[4][4][4];
    #pragma unroll
    for (int i = 0; i < 4; ++i)
        #pragma unroll
        for (int j = 0; j < 4; ++j)
            #pragma unroll
            for (int k = 0; k < 4; ++k) acc[i][j][k] = 0.f;

    auto load_stage = [&](int slot, int c) {
        const int p  = c / KCH;
        const int ko = (c - p * KCH) * 64;
        const bf16* Asrc = (p == 1) ? Al : Ah;
        const bf16* Bsrc = (p == 2) ? Bl : Bh;
        const uint32_t ab = sb + slot * STAGE_BYTES;
        const uint32_t bb = ab + STAGE_A_BYTES;
        #pragma unroll
        for (int i = 0; i < 4; ++i) {
            const int u = tid + i * 512, r = u >> 3, c8 = u & 7;
            CP_ASYNC16(ab + swz128(r * 128 + c8 * 16),
                       Asrc + (size_t)(m0 + r) * KTOT + ko + c8 * 8);
        }
        #pragma unroll
        for (int i = 0; i < 2; ++i) {
            const int u = tid + i * 512, r = u >> 3, c8 = u & 7;
            CP_ASYNC16(bb + swz128(r * 128 + c8 * 16),
                       Bsrc + (size_t)(n0 + r) * KTOT + ko + c8 * 8);
        }
    };

    // prologue: fill 3 stages
    #pragma unroll
    for (int s = 0; s < 3; ++s) { load_stage(s, s); CP_COMMIT(); }

    const int lrow  = lane & 15;
    const int lhalf = lane >> 4;

    for (int c = 0; c < KC_TOTAL; ++c) {
        CP_WAIT2();
        __syncthreads();

        // issue next-stage loads first so they overlap the compute below
        if (c + 3 < KC_TOTAL) load_stage((c + 3) & 3, c + 3);
        CP_COMMIT();

        const uint32_t ab = sb + (c & 3) * STAGE_BYTES;
        const uint32_t bb = ab + STAGE_A_BYTES;

        // B-fragment double buffer
        uint32_t bfr[2][2][4];
        #pragma unroll
        for (int g = 0; g < 2; ++g) {
            const uint32_t bd = bb + swz128((wn + g * 16 + lrow) * 128 + 0 + lhalf * 16);
            LDSM_X4(bfr[0][g][0], bfr[0][g][1], bfr[0][g][2], bfr[0][g][3], bd);
        }

        #pragma unroll
        for (int kk = 0; kk < 4; ++kk) {
            uint32_t afr[4][4];
            #pragma unroll
            for (int mi = 0; mi < 4; ++mi) {
                const uint32_t ad = ab + swz128((wm + mi * 16 + lrow) * 128 + kk * 32 + lhalf * 16);
                LDSM_X4(afr[mi][0], afr[mi][1], afr[mi][2], afr[mi][3], ad);
            }
            if (kk < 3) {
                #pragma unroll
                for (int g = 0; g < 2; ++g) {
                    const uint32_t bd = bb + swz128((wn + g * 16 + lrow) * 128 + (kk + 1) * 32 + lhalf * 16);
                    LDSM_X4(bfr[(kk + 1) & 1][g][0], bfr[(kk + 1) & 1][g][1],
                            bfr[(kk + 1) & 1][g][2], bfr[(kk + 1) & 1][g][3], bd);
                }
            }
            #pragma unroll
            for (int mi = 0; mi < 4; ++mi) {
                #pragma unroll
                for (int nj = 0; nj < 4; ++nj) {
                    const int g = nj >> 1, h = nj & 1;
                    MMA_BF16(acc[mi][nj], afr[mi],
                             bfr[kk & 1][g][h ? 1 : 0], bfr[kk & 1][g][h ? 3 : 2]);
                }
            }
        }
    }

    // ---------------- epilogue ----------------------------------------------
    const int erow = lane >> 2;          // 0..7
    const int ecol = (lane & 3) * 2;     // 0,2,4,6

    #pragma unroll
    for (int mi = 0; mi < 4; ++mi) {
        #pragma unroll
        for (int nj = 0; nj < 4; ++nj) {
            const int n = n0 + wn + nj * 8 + ecol;
            const float2 b2 = *reinterpret_cast<const float2*>(bias + n);
            #pragma unroll
            for (int half = 0; half < 2; ++half) {
                const int m = m0 + wm + mi * 16 + erow + half * 8;
                const float v0 = acc[mi][nj][half * 2 + 0] + b2.x;
                const float v1 = acc[mi][nj][half * 2 + 1] + b2.y;
                const size_t idx = (size_t)m * NTOT + n;
                if (EPI == TCG_EPI_TANH) {
                    const float t0 = tanhf(v0), t1 = tanhf(v1);
                    const bf16 h0 = __float2bfloat16(t0);
                    const bf16 h1 = __float2bfloat16(t1);
                    const bf16 l0 = __float2bfloat16(t0 - __bfloat162float(h0));
                    const bf16 l1 = __float2bfloat16(t1 - __bfloat162float(h1));
                    *reinterpret_cast<uint32_t*>(outHi + idx) = bf2u(h0, h1);
                    *reinterpret_cast<uint32_t*>(outLo + idx) = bf2u(l0, l1);
                } else {
                    const float2 ho = *reinterpret_cast<const float2*>(h_old + idx);
                    const float2 xe = *reinterpret_cast<const float2*>(xemb + idx);
                    float2 o;
                    o.x = 0.5f * ho.x + 0.5f * (v0 + xe.x);
                    o.y = 0.5f * ho.y + 0.5f * (v1 + xe.y);
                    *reinterpret_cast<float2*>(outF + idx) = o;
                }
            }
        }
    }
}

// ---------------- fp32 SGEMM (embed / head) ---------------------------------
#define EPI_BIAS        0
#define EPI_BIAS_COPY2  1

template <int EPI>
__global__ __launch_bounds__(256, 2)
void sgemm_nt(int M, int N, int K,
              const float* __restrict__ A, const float* __restrict__ Bm,
              const float* __restrict__ bias, float* __restrict__ C,
              float* __restrict__ C2)
{
    __shared__ __align__(16) float As[2][8][128];
    __shared__ __align__(16) float Bs[2][8][128];
    const int tid = threadIdx.x;
    const int m0 = blockIdx.y * 128, n0 = blockIdx.x * 128;
    const int lr = tid >> 1, lk = (tid & 1) * 4;
    const int arow = m0 + lr, brow = n0 + lr;
    const bool bvalid = (brow < N);
    const int cm = (tid >> 4) * 8, cn = (tid & 15) * 8;

    float acc[8][8];
    #pragma unroll
    for (int i = 0; i < 8; ++i)
        #pragma unroll
        for (int j = 0; j < 8; ++j) acc[i][j] = 0.f;

    const int nk = K >> 3;
    float4 a4 = *reinterpret_cast<const float4*>(A + (size_t)arow * K + lk);
    float4 b4 = make_float4(0.f, 0.f, 0.f, 0.f);
    if (bvalid) b4 = *reinterpret_cast<const float4*>(Bm + (size_t)brow * K + lk);
    As[0][lk+0][lr]=a4.x; As[0][lk+1][lr]=a4.y; As[0][lk+2][lr]=a4.z; As[0][lk+3][lr]=a4.w;
    Bs[0][lk+0][lr]=b4.x; Bs[0][lk+1][lr]=b4.y; Bs[0][lk+2][lr]=b4.z; Bs[0][lk+3][lr]=b4.w;
    __syncthreads();

    int buf = 0;
    for (int kt = 0; kt < nk; ++kt) {
        const bool nx = (kt + 1) < nk;
        if (nx) {
            const int ko = (kt + 1) * 8 + lk;
            a4 = *reinterpret_cast<const float4*>(A + (size_t)arow * K + ko);
            b4 = bvalid ? *reinterpret_cast<const float4*>(Bm + (size_t)brow * K + ko)
                        : make_float4(0.f, 0.f, 0.f, 0.f);
        }
        #pragma unroll
        for (int k = 0; k < 8; ++k) {
            float af[8], bf[8];
            *reinterpret_cast<float4*>(af)   = *reinterpret_cast<const float4*>(&As[buf][k][cm]);
            *reinterpret_cast<float4*>(af+4) = *reinterpret_cast<const float4*>(&As[buf][k][cm+4]);
            *reinterpret_cast<float4*>(bf)   = *reinterpret_cast<const float4*>(&Bs[buf][k][cn]);
            *reinterpret_cast<float4*>(bf+4) = *reinterpret_cast<const float4*>(&Bs[buf][k][cn+4]);
            #pragma unroll
            for (int i = 0; i < 8; ++i)
                #pragma unroll
                for (int j = 0; j < 8; ++j) acc[i][j] = fmaf(af[i], bf[j], acc[i][j]);
        }
        if (nx) {
            const int nb = buf ^ 1;
            As[nb][lk+0][lr]=a4.x; As[nb][lk+1][lr]=a4.y; As[nb][lk+2][lr]=a4.z; As[nb][lk+3][lr]=a4.w;
            Bs[nb][lk+0][lr]=b4.x; Bs[nb][lk+1][lr]=b4.y; Bs[nb][lk+2][lr]=b4.z; Bs[nb][lk+3][lr]=b4.w;
            __syncthreads();
            buf = nb;
        }
    }
    #pragma unroll
    for (int i = 0; i < 8; ++i) {
        const int m = m0 + cm + i;
        #pragma unroll
        for (int j = 0; j < 8; ++j) {
            const int n = n0 + cn + j;
            if (n < N) {
                const float v = acc[i][j] + bias[n];
                const size_t idx = (size_t)m * N + n;
                C[idx] = v;
                if (EPI == EPI_BIAS_COPY2) C2[idx] = v;
            }
        }
    }
}

// ---------------- LayerNorm -> (hi, lo) bf16 --------------------------------
__device__ __forceinline__ float block_sum_256(float v, float* sh)
{
    #pragma unroll
    for (int o = 16; o > 0; o >>= 1) v += __shfl_xor_sync(0xffffffffu, v, o);
    const int w = threadIdx.x >> 5;
    __syncthreads();
    if ((threadIdx.x & 31) == 0) sh[w] = v;
    __syncthreads();
    float r = 0.f;
    if (threadIdx.x < 8) r = sh[threadIdx.x];
    if (threadIdx.x < 32) {
        #pragma unroll
        for (int o = 4; o > 0; o >>= 1) r += __shfl_xor_sync(0xffffffffu, r, o);
        if (threadIdx.x == 0) sh[0] = r;
    }
    __syncthreads();
    return sh[0];
}

__global__ void layernorm_split_kernel(const float* __restrict__ h,
                                       const float* __restrict__ w,
                                       const float* __restrict__ b,
                                       bf16* __restrict__ ohi, bf16* __restrict__ olo)
{
    __shared__ float sh[8];
    const int row = blockIdx.x, tid = threadIdx.x;
    const float4 v = reinterpret_cast<const float4*>(h + (size_t)row * HDIM)[tid];
    float s = v.x + v.y + v.z + v.w;
    const float mean = block_sum_256(s, sh) * (1.f / HDIM);
    const float dx=v.x-mean, dy=v.y-mean, dz=v.z-mean, dw=v.w-mean;
    float sq = dx*dx + dy*dy + dz*dz + dw*dw;
    const float var = block_sum_256(sq, sh) * (1.f / HDIM);
    const float rstd = rsqrtf(var + LN_EPS);
    const float4 w4 = reinterpret_cast<const float4*>(w)[tid];
    const float4 b4 = reinterpret_cast<const float4*>(b)[tid];
    float o[4];
    o[0]=dx*rstd*w4.x+b4.x; o[1]=dy*rstd*w4.y+b4.y;
    o[2]=dz*rstd*w4.z+b4.z; o[3]=dw*rstd*w4.w+b4.w;
    bf16 hi[4], lo[4];
    #pragma unroll
    for (int k = 0; k < 4; ++k) {
        hi[k] = __float2bfloat16(o[k]);
        lo[k] = __float2bfloat16(o[k] - __bfloat162float(hi[k]));
    }
    const size_t idx = (size_t)row * HDIM + tid * 4;
    uint2 wh; wh.x = bf2u(hi[0], hi[1]); wh.y = bf2u(hi[2], hi[3]);
    uint2 wl; wl.x = bf2u(lo[0], lo[1]); wl.y = bf2u(lo[2], lo[3]);
    *reinterpret_cast<uint2*>(ohi + idx) = wh;
    *reinterpret_cast<uint2*>(olo + idx) = wl;
}

// ---------------- fp32 -> (hi, lo) bf16 split -------------------------------
__global__ void split_kernel(const float* __restrict__ src,
                             bf16* __restrict__ hi, bf16* __restrict__ lo, int n)
{
    for (int i = 4 * (blockIdx.x * blockDim.x + threadIdx.x); i < n;
         i += 4 * gridDim.x * blockDim.x) {
        const float4 v = *reinterpret_cast<const float4*>(src + i);
        bf16 h[4], l[4];
        const float vv[4] = {v.x, v.y, v.z, v.w};
        #pragma unroll
        for (int k = 0; k < 4; ++k) {
            h[k] = __float2bfloat16(vv[k]);
            l[k] = __float2bfloat16(vv[k] - __bfloat162float(h[k]));
        }
        uint2 wh; wh.x = bf2u(h[0], h[1]); wh.y = bf2u(h[2], h[3]);
        uint2 wl; wl.x = bf2u(l[0], l[1]); wl.y = bf2u(l[2], l[3]);
        *reinterpret_cast<uint2*>(hi + i) = wh;
        *reinterpret_cast<uint2*>(lo + i) = wl;
    }
}

// ---------------- launch -----------------------------------------------------
extern "C" void kernel_launch(void* const* d_in, const int* in_sizes, int n_in,
                              void* d_out, int out_size)
{
    const float* x       = (const float*)d_in[0];
    const float* embed_w = (const float*)d_in[1];
    const float* embed_b = (const float*)d_in[2];
    const float* W1_w    = (const float*)d_in[3];
    const float* W1_b    = (const float*)d_in[4];
    const float* W2_w    = (const float*)d_in[5];
    const float* W2_b    = (const float*)d_in[6];
    const float* norm_w  = (const float*)d_in[7];
    const float* norm_b  = (const float*)d_in[8];
    const float* head_w  = (const float*)d_in[9];
    const float* head_b  = (const float*)d_in[10];

    float *p_xemb, *p_h;
    bf16 *p_hn_hi, *p_hn_lo, *p_hid_hi, *p_hid_lo;
    bf16 *p_w1_hi, *p_w1_lo, *p_w2_hi, *p_w2_lo;
    cudaGetSymbolAddress((void**)&p_xemb,   g_xemb);
    cudaGetSymbolAddress((void**)&p_h,      g_h);
    cudaGetSymbolAddress((void**)&p_hn_hi,  g_hn_hi);
    cudaGetSymbolAddress((void**)&p_hn_lo,  g_hn_lo);
    cudaGetSymbolAddress((void**)&p_hid_hi, g_hid_hi);
    cudaGetSymbolAddress((void**)&p_hid_lo, g_hid_lo);
    cudaGetSymbolAddress((void**)&p_w1_hi,  g_w1_hi);
    cudaGetSymbolAddress((void**)&p_w1_lo,  g_w1_lo);
    cudaGetSymbolAddress((void**)&p_w2_hi,  g_w2_hi);
    cudaGetSymbolAddress((void**)&p_w2_lo,  g_w2_lo);

    float* out = (float*)d_out;

    cudaFuncSetAttribute((const void*)hmma_gemm<HDIM,   FFNDIM, TCG_EPI_TANH>,
                         cudaFuncAttributeMaxDynamicSharedMemorySize, SMEM_MMA);
    cudaFuncSetAttribute((const void*)hmma_gemm<FFNDIM, HDIM,   TCG_EPI_STEP>,
                         cudaFuncAttributeMaxDynamicSharedMemorySize, SMEM_MMA);

    // weight splits
    split_kernel<<<512, 256>>>(W1_w, p_w1_hi, p_w1_lo, FFNDIM * HDIM);
    split_kernel<<<512, 256>>>(W2_w, p_w2_hi, p_w2_lo, HDIM * FFNDIM);

    // x_emb = x @ embed_w^T + embed_b ; h0 = x_emb
    sgemm_nt<EPI_BIAS_COPY2><<<dim3(HDIM / 128, BROWS / 128), 256>>>(
        BROWS, HDIM, DIN, x, embed_w, embed_b, p_xemb, p_h);

    for (int s = 0; s < NSTEPS; ++s) {
        layernorm_split_kernel<<<BROWS, 256>>>(p_h, norm_w, norm_b, p_hn_hi, p_hn_lo);

        // hidden = tanh(hnorm @ W1^T + b1) -> (hi, lo) bf16
        hmma_gemm<HDIM, FFNDIM, TCG_EPI_TANH>
            <<<dim3(FFNDIM / 128, BROWS / 256), 512, SMEM_MMA>>>(
            p_hn_hi, p_hn_lo, p_w1_hi, p_w1_lo, W1_b,
            p_hid_hi, p_hid_lo, nullptr, nullptr, nullptr);

        // h = 0.5*h + 0.5*(hidden @ W2^T + b2 + xemb)
        hmma_gemm<FFNDIM, HDIM, TCG_EPI_STEP>
            <<<dim3(HDIM / 128, BROWS / 256), 512, SMEM_MMA>>>(
            p_hid_hi, p_hid_lo, p_w2_hi, p_w2_lo, W2_b,
            nullptr, nullptr, p_h, p_h, p_xemb);
    }

    // out = h @ head_w^T + head_b
    sgemm_nt<EPI_BIAS><<<dim3((DOUT + 127) / 128, BROWS / 128), 256>>>(
        BROWS, DOUT, HDIM, p_h, head_w, head_b, out, nullptr);
}

// round 12
// speedup vs baseline: 1.1362x; 1.1362x over previous
#include <cuda_runtime.h>
#include <cuda_bf16.h>
#include <math.h>
#include <stdint.h>

#define BROWS  4096
#define HDIM   1024
#define FFNDIM 4096
#define DIN    784
#define DOUT   1000
#define NSTEPS 30
#define LN_EPS 1e-5f

typedef __nv_bfloat16 bf16;

// ---------------- scratch ---------------------------------------------------
__device__ __align__(256) float g_xemb[(size_t)BROWS * HDIM];
__device__ __align__(256) float g_h   [(size_t)BROWS * HDIM];
__device__ __align__(256) bf16  g_hn_hi [(size_t)BROWS * HDIM];
__device__ __align__(256) bf16  g_hn_lo [(size_t)BROWS * HDIM];
__device__ __align__(256) bf16  g_hid_hi[(size_t)BROWS * FFNDIM];
__device__ __align__(256) bf16  g_hid_lo[(size_t)BROWS * FFNDIM];
__device__ __align__(256) bf16  g_w1_hi[(size_t)FFNDIM * HDIM];
__device__ __align__(256) bf16  g_w1_lo[(size_t)FFNDIM * HDIM];
__device__ __align__(256) bf16  g_w2_hi[(size_t)HDIM * FFNDIM];
__device__ __align__(256) bf16  g_w2_lo[(size_t)HDIM * FFNDIM];

// ---------------- helpers ---------------------------------------------------
__device__ __forceinline__ uint32_t smem_u32(const void* p) {
    uint32_t a;
    asm("{ .reg .u64 t; cvta.to.shared.u64 t, %1; cvt.u32.u64 %0, t; }" : "=r"(a) : "l"(p));
    return a;
}
static __device__ __forceinline__ uint32_t swz128(uint32_t off) {
    return off ^ ((off >> 3) & 0x70u);
}
__device__ __forceinline__ uint32_t bf2u(bf16 a, bf16 b) {
    unsigned short ua = *reinterpret_cast<unsigned short*>(&a);
    unsigned short ub = *reinterpret_cast<unsigned short*>(&b);
    return (uint32_t)ua | ((uint32_t)ub << 16);
}

#define CP_ASYNC16(saddr, gptr) \
    asm volatile("cp.async.cg.shared.global [%0], [%1], 16;" :: "r"(saddr), "l"(gptr) : "memory")
#define CP_COMMIT() asm volatile("cp.async.commit_group;" ::: "memory")
#define CP_WAIT1()  asm volatile("cp.async.wait_group 1;" ::: "memory")

#define LDSM_X4(r0, r1, r2, r3, addr) \
    asm volatile("ldmatrix.sync.aligned.m8n8.x4.shared.b16 {%0,%1,%2,%3}, [%4];" \
        : "=r"(r0), "=r"(r1), "=r"(r2), "=r"(r3) : "r"(addr))

#define MMA_BF16(d, a, b0, b1) \
    asm volatile("mma.sync.aligned.m16n8k16.row.col.f32.bf16.bf16.f32 " \
        "{%0,%1,%2,%3}, {%4,%5,%6,%7}, {%8,%9}, {%0,%1,%2,%3};" \
        : "+f"((d)[0]), "+f"((d)[1]), "+f"((d)[2]), "+f"((d)[3]) \
        : "r"((a)[0]), "r"((a)[1]), "r"((a)[2]), "r"((a)[3]), "r"(b0), "r"(b1))

// ---------------- split-bf16 HMMA GEMM --------------------------------------
// D[M,N] = A[M,K] @ B[N,K]^T, A = Ah+Al, B = Bh+Bl (K-concat, 3 phases).
// CTA tile 128x128, 256 threads (8 warps = 2m x 4n, warp tile 64x32).
// BK=64, 3-stage cp.async pipeline, 96KB smem -> 2 CTAs/SM.
#define TCG_EPI_TANH 0
#define TCG_EPI_STEP 1

#define NSTG 3
#define STAGE_A_BYTES 16384            // 128 rows x 128B
#define STAGE_BYTES   32768            // A + B
#define SMEM_MMA (NSTG * STAGE_BYTES)  // 96 KB

template <int KTOT, int NTOT, int EPI>
__global__ __launch_bounds__(256, 2)
void hmma_gemm(const bf16* __restrict__ Ah, const bf16* __restrict__ Al,
               const bf16* __restrict__ Bh, const bf16* __restrict__ Bl,
               const float* __restrict__ bias,
               bf16*  __restrict__ outHi, bf16* __restrict__ outLo,
               float* __restrict__ outF,
               const float* __restrict__ h_old, const float* __restrict__ xemb)
{
    constexpr int KCH = KTOT / 64;
    constexpr int KC_TOTAL = 3 * KCH;

    extern __shared__ __align__(1024) char smem[];
    const uint32_t sb = smem_u32(smem);

    const int tid  = threadIdx.x;
    const int wid  = tid >> 5;
    const int lane = tid & 31;
    const int m0 = blockIdx.y * 128;
    const int n0 = blockIdx.x * 128;
    const int wm = (wid >> 2) * 64;    // 0 / 64
    const int wn = (wid & 3) * 32;     // 0..96

    float acc[4][4][4];
    #pragma unroll
    for (int i = 0; i < 4; ++i)
        #pragma unroll
        for (int j = 0; j < 4; ++j)
            #pragma unroll
            for (int k = 0; k < 4; ++k) acc[i][j][k] = 0.f;

    auto load_stage = [&](int slot, int c) {
        const int p  = c / KCH;
        const int ko = (c - p * KCH) * 64;
        const bf16* Asrc = (p == 1) ? Al : Ah;
        const bf16* Bsrc = (p == 2) ? Bl : Bh;
        const uint32_t ab = sb + slot * STAGE_BYTES;
        const uint32_t bb = ab + STAGE_A_BYTES;
        #pragma unroll
        for (int i = 0; i < 4; ++i) {
            const int u = tid + i * 256, r = u >> 3, c8 = u & 7;
            CP_ASYNC16(ab + swz128(r * 128 + c8 * 16),
                       Asrc + (size_t)(m0 + r) * KTOT + ko + c8 * 8);
        }
        #pragma unroll
        for (int i = 0; i < 4; ++i) {
            const int u = tid + i * 256, r = u >> 3, c8 = u & 7;
            CP_ASYNC16(bb + swz128(r * 128 + c8 * 16),
                       Bsrc + (size_t)(n0 + r) * KTOT + ko + c8 * 8);
        }
    };

    // prologue: fill 2 stages
    load_stage(0, 0); CP_COMMIT();
    load_stage(1, 1); CP_COMMIT();

    const int lrow  = lane & 15;
    const int lhalf = lane >> 4;

    int rs = 0;
    for (int c = 0; c < KC_TOTAL; ++c) {
        CP_WAIT1();
        __syncthreads();

        const uint32_t ab = sb + rs * STAGE_BYTES;
        const uint32_t bb = ab + STAGE_A_BYTES;

        #pragma unroll
        for (int kk = 0; kk < 64; kk += 16) {
            uint32_t afr[4][4];
            #pragma unroll
            for (int mi = 0; mi < 4; ++mi) {
                const uint32_t ad = ab + swz128((wm + mi * 16 + lrow) * 128 + kk * 2 + lhalf * 16);
                LDSM_X4(afr[mi][0], afr[mi][1], afr[mi][2], afr[mi][3], ad);
            }
            uint32_t bfr[2][4];
            #pragma unroll
            for (int g = 0; g < 2; ++g) {
                const uint32_t bd = bb + swz128((wn + g * 16 + lrow) * 128 + kk * 2 + lhalf * 16);
                LDSM_X4(bfr[g][0], bfr[g][1], bfr[g][2], bfr[g][3], bd);
            }
            #pragma unroll
            for (int mi = 0; mi < 4; ++mi) {
                #pragma unroll
                for (int nj = 0; nj < 4; ++nj) {
                    const int g = nj >> 1, h = nj & 1;
                    MMA_BF16(acc[mi][nj], afr[mi], bfr[g][h ? 1 : 0], bfr[g][h ? 3 : 2]);
                }
            }
        }

        if (c + 2 < KC_TOTAL) {
            int ws = rs + 2; if (ws >= NSTG) ws -= NSTG;
            load_stage(ws, c + 2);
        }
        CP_COMMIT();
        __syncthreads();
        if (++rs == NSTG) rs = 0;
    }

    // ---------------- epilogue ----------------------------------------------
    const int erow = lane >> 2;          // 0..7
    const int ecol = (lane & 3) * 2;     // 0,2,4,6

    #pragma unroll
    for (int mi = 0; mi < 4; ++mi) {
        #pragma unroll
        for (int nj = 0; nj < 4; ++nj) {
            const int n = n0 + wn + nj * 8 + ecol;
            const float2 b2 = *reinterpret_cast<const float2*>(bias + n);
            #pragma unroll
            for (int half = 0; half < 2; ++half) {
                const int m = m0 + wm + mi * 16 + erow + half * 8;
                const float v0 = acc[mi][nj][half * 2 + 0] + b2.x;
                const float v1 = acc[mi][nj][half * 2 + 1] + b2.y;
                const size_t idx = (size_t)m * NTOT + n;
                if (EPI == TCG_EPI_TANH) {
                    const float t0 = tanhf(v0), t1 = tanhf(v1);
                    const bf16 h0 = __float2bfloat16(t0);
                    const bf16 h1 = __float2bfloat16(t1);
                    const bf16 l0 = __float2bfloat16(t0 - __bfloat162float(h0));
                    const bf16 l1 = __float2bfloat16(t1 - __bfloat162float(h1));
                    *reinterpret_cast<uint32_t*>(outHi + idx) = bf2u(h0, h1);
                    *reinterpret_cast<uint32_t*>(outLo + idx) = bf2u(l0, l1);
                } else {
                    const float2 ho = *reinterpret_cast<const float2*>(h_old + idx);
                    const float2 xe = *reinterpret_cast<const float2*>(xemb + idx);
                    float2 o;
                    o.x = 0.5f * ho.x + 0.5f * (v0 + xe.x);
                    o.y = 0.5f * ho.y + 0.5f * (v1 + xe.y);
                    *reinterpret_cast<float2*>(outF + idx) = o;
                }
            }
        }
    }
}

// ---------------- fp32 SGEMM (embed / head) ---------------------------------
#define EPI_BIAS        0
#define EPI_BIAS_COPY2  1

template <int EPI>
__global__ __launch_bounds__(256, 2)
void sgemm_nt(int M, int N, int K,
              const float* __restrict__ A, const float* __restrict__ Bm,
              const float* __restrict__ bias, float* __restrict__ C,
              float* __restrict__ C2)
{
    __shared__ __align__(16) float As[2][8][128];
    __shared__ __align__(16) float Bs[2][8][128];
    const int tid = threadIdx.x;
    const int m0 = blockIdx.y * 128, n0 = blockIdx.x * 128;
    const int lr = tid >> 1, lk = (tid & 1) * 4;
    const int arow = m0 + lr, brow = n0 + lr;
    const bool bvalid = (brow < N);
    const int cm = (tid >> 4) * 8, cn = (tid & 15) * 8;

    float acc[8][8];
    #pragma unroll
    for (int i = 0; i < 8; ++i)
        #pragma unroll
        for (int j = 0; j < 8; ++j) acc[i][j] = 0.f;

    const int nk = K >> 3;
    float4 a4 = *reinterpret_cast<const float4*>(A + (size_t)arow * K + lk);
    float4 b4 = make_float4(0.f, 0.f, 0.f, 0.f);
    if (bvalid) b4 = *reinterpret_cast<const float4*>(Bm + (size_t)brow * K + lk);
    As[0][lk+0][lr]=a4.x; As[0][lk+1][lr]=a4.y; As[0][lk+2][lr]=a4.z; As[0][lk+3][lr]=a4.w;
    Bs[0][lk+0][lr]=b4.x; Bs[0][lk+1][lr]=b4.y; Bs[0][lk+2][lr]=b4.z; Bs[0][lk+3][lr]=b4.w;
    __syncthreads();

    int buf = 0;
    for (int kt = 0; kt < nk; ++kt) {
        const bool nx = (kt + 1) < nk;
        if (nx) {
            const int ko = (kt + 1) * 8 + lk;
            a4 = *reinterpret_cast<const float4*>(A + (size_t)arow * K + ko);
            b4 = bvalid ? *reinterpret_cast<const float4*>(Bm + (size_t)brow * K + ko)
                        : make_float4(0.f, 0.f, 0.f, 0.f);
        }
        #pragma unroll
        for (int k = 0; k < 8; ++k) {
            float af[8], bf[8];
            *reinterpret_cast<float4*>(af)   = *reinterpret_cast<const float4*>(&As[buf][k][cm]);
            *reinterpret_cast<float4*>(af+4) = *reinterpret_cast<const float4*>(&As[buf][k][cm+4]);
            *reinterpret_cast<float4*>(bf)   = *reinterpret_cast<const float4*>(&Bs[buf][k][cn]);
            *reinterpret_cast<float4*>(bf+4) = *reinterpret_cast<const float4*>(&Bs[buf][k][cn+4]);
            #pragma unroll
            for (int i = 0; i < 8; ++i)
                #pragma unroll
                for (int j = 0; j < 8; ++j) acc[i][j] = fmaf(af[i], bf[j], acc[i][j]);
        }
        if (nx) {
            const int nb = buf ^ 1;
            As[nb][lk+0][lr]=a4.x; As[nb][lk+1][lr]=a4.y; As[nb][lk+2][lr]=a4.z; As[nb][lk+3][lr]=a4.w;
            Bs[nb][lk+0][lr]=b4.x; Bs[nb][lk+1][lr]=b4.y; Bs[nb][lk+2][lr]=b4.z; Bs[nb][lk+3][lr]=b4.w;
            __syncthreads();
            buf = nb;
        }
    }
    #pragma unroll
    for (int i = 0; i < 8; ++i) {
        const int m = m0 + cm + i;
        #pragma unroll
        for (int j = 0; j < 8; ++j) {
            const int n = n0 + cn + j;
            if (n < N) {
                const float v = acc[i][j] + bias[n];
                const size_t idx = (size_t)m * N + n;
                C[idx] = v;
                if (EPI == EPI_BIAS_COPY2) C2[idx] = v;
            }
        }
    }
}

// ---------------- LayerNorm -> (hi, lo) bf16 --------------------------------
__device__ __forceinline__ float block_sum_256(float v, float* sh)
{
    #pragma unroll
    for (int o = 16; o > 0; o >>= 1) v += __shfl_xor_sync(0xffffffffu, v, o);
    const int w = threadIdx.x >> 5;
    __syncthreads();
    if ((threadIdx.x & 31) == 0) sh[w] = v;
    __syncthreads();
    float r = 0.f;
    if (threadIdx.x < 8) r = sh[threadIdx.x];
    if (threadIdx.x < 32) {
        #pragma unroll
        for (int o = 4; o > 0; o >>= 1) r += __shfl_xor_sync(0xffffffffu, r, o);
        if (threadIdx.x == 0) sh[0] = r;
    }
    __syncthreads();
    return sh[0];
}

__global__ void layernorm_split_kernel(const float* __restrict__ h,
                                       const float* __restrict__ w,
                                       const float* __restrict__ b,
                                       bf16* __restrict__ ohi, bf16* __restrict__ olo)
{
    __shared__ float sh[8];
    const int row = blockIdx.x, tid = threadIdx.x;
    const float4 v = reinterpret_cast<const float4*>(h + (size_t)row * HDIM)[tid];
    float s = v.x + v.y + v.z + v.w;
    const float mean = block_sum_256(s, sh) * (1.f / HDIM);
    const float dx=v.x-mean, dy=v.y-mean, dz=v.z-mean, dw=v.w-mean;
    float sq = dx*dx + dy*dy + dz*dz + dw*dw;
    const float var = block_sum_256(sq, sh) * (1.f / HDIM);
    const float rstd = rsqrtf(var + LN_EPS);
    const float4 w4 = reinterpret_cast<const float4*>(w)[tid];
    const float4 b4 = reinterpret_cast<const float4*>(b)[tid];
    float o[4];
    o[0]=dx*rstd*w4.x+b4.x; o[1]=dy*rstd*w4.y+b4.y;
    o[2]=dz*rstd*w4.z+b4.z; o[3]=dw*rstd*w4.w+b4.w;
    bf16 hi[4], lo[4];
    #pragma unroll
    for (int k = 0; k < 4; ++k) {
        hi[k] = __float2bfloat16(o[k]);
        lo[k] = __float2bfloat16(o[k] - __bfloat162float(hi[k]));
    }
    const size_t idx = (size_t)row * HDIM + tid * 4;
    uint2 wh; wh.x = bf2u(hi[0], hi[1]); wh.y = bf2u(hi[2], hi[3]);
    uint2 wl; wl.x = bf2u(lo[0], lo[1]); wl.y = bf2u(lo[2], lo[3]);
    *reinterpret_cast<uint2*>(ohi + idx) = wh;
    *reinterpret_cast<uint2*>(olo + idx) = wl;
}

// ---------------- fp32 -> (hi, lo) bf16 split -------------------------------
__global__ void split_kernel(const float* __restrict__ src,
                             bf16* __restrict__ hi, bf16* __restrict__ lo, int n)
{
    for (int i = 4 * (blockIdx.x * blockDim.x + threadIdx.x); i < n;
         i += 4 * gridDim.x * blockDim.x) {
        const float4 v = *reinterpret_cast<const float4*>(src + i);
        bf16 h[4], l[4];
        const float vv[4] = {v.x, v.y, v.z, v.w};
        #pragma unroll
        for (int k = 0; k < 4; ++k) {
            h[k] = __float2bfloat16(vv[k]);
            l[k] = __float2bfloat16(vv[k] - __bfloat162float(h[k]));
        }
        uint2 wh; wh.x = bf2u(h[0], h[1]); wh.y = bf2u(h[2], h[3]);
        uint2 wl; wl.x = bf2u(l[0], l[1]); wl.y = bf2u(l[2], l[3]);
        *reinterpret_cast<uint2*>(hi + i) = wh;
        *reinterpret_cast<uint2*>(lo + i) = wl;
    }
}

// ---------------- launch -----------------------------------------------------
extern "C" void kernel_launch(void* const* d_in, const int* in_sizes, int n_in,
                              void* d_out, int out_size)
{
    const float* x       = (const float*)d_in[0];
    const float* embed_w = (const float*)d_in[1];
    const float* embed_b = (const float*)d_in[2];
    const float* W1_w    = (const float*)d_in[3];
    const float* W1_b    = (const float*)d_in[4];
    const float* W2_w    = (const float*)d_in[5];
    const float* W2_b    = (const float*)d_in[6];
    const float* norm_w  = (const float*)d_in[7];
    const float* norm_b  = (const float*)d_in[8];
    const float* head_w  = (const float*)d_in[9];
    const float* head_b  = (const float*)d_in[10];

    float *p_xemb, *p_h;
    bf16 *p_hn_hi, *p_hn_lo, *p_hid_hi, *p_hid_lo;
    bf16 *p_w1_hi, *p_w1_lo, *p_w2_hi, *p_w2_lo;
    cudaGetSymbolAddress((void**)&p_xemb,   g_xemb);
    cudaGetSymbolAddress((void**)&p_h,      g_h);
    cudaGetSymbolAddress((void**)&p_hn_hi,  g_hn_hi);
    cudaGetSymbolAddress((void**)&p_hn_lo,  g_hn_lo);
    cudaGetSymbolAddress((void**)&p_hid_hi, g_hid_hi);
    cudaGetSymbolAddress((void**)&p_hid_lo, g_hid_lo);
    cudaGetSymbolAddress((void**)&p_w1_hi,  g_w1_hi);
    cudaGetSymbolAddress((void**)&p_w1_lo,  g_w1_lo);
    cudaGetSymbolAddress((void**)&p_w2_hi,  g_w2_hi);
    cudaGetSymbolAddress((void**)&p_w2_lo,  g_w2_lo);

    float* out = (float*)d_out;

    cudaFuncSetAttribute((const void*)hmma_gemm<HDIM,   FFNDIM, TCG_EPI_TANH>,
                         cudaFuncAttributeMaxDynamicSharedMemorySize, SMEM_MMA);
    cudaFuncSetAttribute((const void*)hmma_gemm<FFNDIM, HDIM,   TCG_EPI_STEP>,
                         cudaFuncAttributeMaxDynamicSharedMemorySize, SMEM_MMA);

    // weight splits
    split_kernel<<<512, 256>>>(W1_w, p_w1_hi, p_w1_lo, FFNDIM * HDIM);
    split_kernel<<<512, 256>>>(W2_w, p_w2_hi, p_w2_lo, HDIM * FFNDIM);

    // x_emb = x @ embed_w^T + embed_b ; h0 = x_emb
    sgemm_nt<EPI_BIAS_COPY2><<<dim3(HDIM / 128, BROWS / 128), 256>>>(
        BROWS, HDIM, DIN, x, embed_w, embed_b, p_xemb, p_h);

    for (int s = 0; s < NSTEPS; ++s) {
        layernorm_split_kernel<<<BROWS, 256>>>(p_h, norm_w, norm_b, p_hn_hi, p_hn_lo);

        // hidden = tanh(hnorm @ W1^T + b1) -> (hi, lo) bf16
        hmma_gemm<HDIM, FFNDIM, TCG_EPI_TANH>
            <<<dim3(FFNDIM / 128, BROWS / 128), 256, SMEM_MMA>>>(
            p_hn_hi, p_hn_lo, p_w1_hi, p_w1_lo, W1_b,
            p_hid_hi, p_hid_lo, nullptr, nullptr, nullptr);

        // h = 0.5*h + 0.5*(hidden @ W2^T + b2 + xemb)
        hmma_gemm<FFNDIM, HDIM, TCG_EPI_STEP>
            <<<dim3(HDIM / 128, BROWS / 128), 256, SMEM_MMA>>>(
            p_hid_hi, p_hid_lo, p_w2_hi, p_w2_lo, W2_b,
            nullptr, nullptr, p_h, p_h, p_xemb);
    }

    // out = h @ head_w^T + head_b
    sgemm_nt<EPI_BIAS><<<dim3((DOUT + 127) / 128, BROWS / 128), 256>>>(
        BROWS, DOUT, HDIM, p_h, head_w, head_b, out, nullptr);
}

// round 14
// speedup vs baseline: 1.5552x; 1.3688x over previous
#include <cuda_runtime.h>
#include <cuda_fp16.h>
#include <math.h>
#include <stdint.h>

#define BROWS  4096
#define HDIM   1024
#define FFNDIM 4096
#define DIN    784
#define DOUT   1000
#define NSTEPS 30
#define LN_EPS 1e-5f

typedef __half fp16;

// ---------------- scratch ---------------------------------------------------
__device__ __align__(256) float g_xemb[(size_t)BROWS * HDIM];
__device__ __align__(256) float g_h   [(size_t)BROWS * HDIM];
__device__ __align__(256) fp16  g_hn_hi [(size_t)BROWS * HDIM];
__device__ __align__(256) fp16  g_hn_lo [(size_t)BROWS * HDIM];
__device__ __align__(256) fp16  g_hid_hi[(size_t)BROWS * FFNDIM];
__device__ __align__(256) fp16  g_hid_lo[(size_t)BROWS * FFNDIM];
__device__ __align__(256) fp16  g_w1[(size_t)FFNDIM * HDIM];
__device__ __align__(256) fp16  g_w2[(size_t)HDIM * FFNDIM];

// ---------------- helpers ---------------------------------------------------
__device__ __forceinline__ uint32_t smem_u32(const void* p) {
    uint32_t a;
    asm("{ .reg .u64 t; cvta.to.shared.u64 t, %1; cvt.u32.u64 %0, t; }" : "=r"(a) : "l"(p));
    return a;
}
static __device__ __forceinline__ uint32_t swz128(uint32_t off) {
    return off ^ ((off >> 3) & 0x70u);
}
__device__ __forceinline__ uint32_t h2u(fp16 a, fp16 b) {
    return (uint32_t)__half_as_ushort(a) | ((uint32_t)__half_as_ushort(b) << 16);
}

#define CP_ASYNC16(saddr, gptr) \
    asm volatile("cp.async.cg.shared.global [%0], [%1], 16;" :: "r"(saddr), "l"(gptr) : "memory")
#define CP_COMMIT() asm volatile("cp.async.commit_group;" ::: "memory")
#define CP_WAIT1()  asm volatile("cp.async.wait_group 1;" ::: "memory")

#define LDSM_X4(r0, r1, r2, r3, addr) \
    asm volatile("ldmatrix.sync.aligned.m8n8.x4.shared.b16 {%0,%1,%2,%3}, [%4];" \
        : "=r"(r0), "=r"(r1), "=r"(r2), "=r"(r3) : "r"(addr))

#define MMA_FP16(d, a, b0, b1) \
    asm volatile("mma.sync.aligned.m16n8k16.row.col.f32.f16.f16.f32 " \
        "{%0,%1,%2,%3}, {%4,%5,%6,%7}, {%8,%9}, {%0,%1,%2,%3};" \
        : "+f"((d)[0]), "+f"((d)[1]), "+f"((d)[2]), "+f"((d)[3]) \
        : "r"((a)[0]), "r"((a)[1]), "r"((a)[2]), "r"((a)[3]), "r"(b0), "r"(b1))

// ---------------- asymmetric split-fp16 HMMA GEMM ----------------------------
// D[M,N] = A[M,K] @ B[N,K]^T, A = Ah+Al (fp16 2-term), B single fp16.
// K-concat 2 phases: (Ah,B), (Al,B).
// CTA tile 128x128, 256 threads (8 warps = 2m x 4n, warp tile 64x32).
// BK=64, 3-stage cp.async pipeline, 96KB smem -> 2 CTAs/SM.  (R12 structure)
#define TCG_EPI_TANH 0
#define TCG_EPI_STEP 1

#define NSTG 3
#define STAGE_A_BYTES 16384            // 128 rows x 128B
#define STAGE_BYTES   32768            // A + B
#define SMEM_MMA (NSTG * STAGE_BYTES)  // 96 KB

template <int KTOT, int NTOT, int EPI>
__global__ __launch_bounds__(256, 2)
void hmma_gemm(const fp16* __restrict__ Ah, const fp16* __restrict__ Al,
               const fp16* __restrict__ B,
               const float* __restrict__ bias,
               fp16*  __restrict__ outHi, fp16* __restrict__ outLo,
               float* __restrict__ outF,
               const float* __restrict__ h_old, const float* __restrict__ xemb)
{
    constexpr int KCH = KTOT / 64;
    constexpr int KC_TOTAL = 2 * KCH;

    extern __shared__ __align__(1024) char smem[];
    const uint32_t sb = smem_u32(smem);

    const int tid  = threadIdx.x;
    const int wid  = tid >> 5;
    const int lane = tid & 31;
    const int m0 = blockIdx.y * 128;
    const int n0 = blockIdx.x * 128;
    const int wm = (wid >> 2) * 64;    // 0 / 64
    const int wn = (wid & 3) * 32;     // 0..96

    float acc[4][4][4];
    #pragma unroll
    for (int i = 0; i < 4; ++i)
        #pragma unroll
        for (int j = 0; j < 4; ++j)
            #pragma unroll
            for (int k = 0; k < 4; ++k) acc[i][j][k] = 0.f;

    auto load_stage = [&](int slot, int c) {
        const int ko = (c >= KCH ? c - KCH : c) * 64;
        const fp16* Asrc = (c >= KCH) ? Al : Ah;
        const uint32_t ab = sb + slot * STAGE_BYTES;
        const uint32_t bb = ab + STAGE_A_BYTES;
        #pragma unroll
        for (int i = 0; i < 4; ++i) {
            const int u = tid + i * 256, r = u >> 3, c8 = u & 7;
            CP_ASYNC16(ab + swz128(r * 128 + c8 * 16),
                       Asrc + (size_t)(m0 + r) * KTOT + ko + c8 * 8);
        }
        #pragma unroll
        for (int i = 0; i < 4; ++i) {
            const int u = tid + i * 256, r = u >> 3, c8 = u & 7;
            CP_ASYNC16(bb + swz128(r * 128 + c8 * 16),
                       B + (size_t)(n0 + r) * KTOT + ko + c8 * 8);
        }
    };

    // prologue: fill 2 stages
    load_stage(0, 0); CP_COMMIT();
    load_stage(1, 1); CP_COMMIT();

    const int lrow  = lane & 15;
    const int lhalf = lane >> 4;

    int rs = 0;
    for (int c = 0; c < KC_TOTAL; ++c) {
        CP_WAIT1();
        __syncthreads();

        const uint32_t ab = sb + rs * STAGE_BYTES;
        const uint32_t bb = ab + STAGE_A_BYTES;

        #pragma unroll
        for (int kk = 0; kk < 64; kk += 16) {
            uint32_t afr[4][4];
            #pragma unroll
            for (int mi = 0; mi < 4; ++mi) {
                const uint32_t ad = ab + swz128((wm + mi * 16 + lrow) * 128 + kk * 2 + lhalf * 16);
                LDSM_X4(afr[mi][0], afr[mi][1], afr[mi][2], afr[mi][3], ad);
            }
            uint32_t bfr[2][4];
            #pragma unroll
            for (int g = 0; g < 2; ++g) {
                const uint32_t bd = bb + swz128((wn + g * 16 + lrow) * 128 + kk * 2 + lhalf * 16);
                LDSM_X4(bfr[g][0], bfr[g][1], bfr[g][2], bfr[g][3], bd);
            }
            #pragma unroll
            for (int mi = 0; mi < 4; ++mi) {
                #pragma unroll
                for (int nj = 0; nj < 4; ++nj) {
                    const int g = nj >> 1, h = nj & 1;
                    MMA_FP16(acc[mi][nj], afr[mi], bfr[g][h ? 1 : 0], bfr[g][h ? 3 : 2]);
                }
            }
        }

        if (c + 2 < KC_TOTAL) {
            int ws = rs + 2; if (ws >= NSTG) ws -= NSTG;
            load_stage(ws, c + 2);
        }
        CP_COMMIT();
        __syncthreads();
        if (++rs == NSTG) rs = 0;
    }

    // ---------------- epilogue ----------------------------------------------
    const int erow = lane >> 2;          // 0..7
    const int ecol = (lane & 3) * 2;     // 0,2,4,6

    #pragma unroll
    for (int mi = 0; mi < 4; ++mi) {
        #pragma unroll
        for (int nj = 0; nj < 4; ++nj) {
            const int n = n0 + wn + nj * 8 + ecol;
            const float2 b2 = *reinterpret_cast<const float2*>(bias + n);
            #pragma unroll
            for (int half = 0; half < 2; ++half) {
                const int m = m0 + wm + mi * 16 + erow + half * 8;
                const float v0 = acc[mi][nj][half * 2 + 0] + b2.x;
                const float v1 = acc[mi][nj][half * 2 + 1] + b2.y;
                const size_t idx = (size_t)m * NTOT + n;
                if (EPI == TCG_EPI_TANH) {
                    const float t0 = tanhf(v0), t1 = tanhf(v1);
                    const fp16 h0 = __float2half(t0);
                    const fp16 h1 = __float2half(t1);
                    const fp16 l0 = __float2half(t0 - __half2float(h0));
                    const fp16 l1 = __float2half(t1 - __half2float(h1));
                    *reinterpret_cast<uint32_t*>(outHi + idx) = h2u(h0, h1);
                    *reinterpret_cast<uint32_t*>(outLo + idx) = h2u(l0, l1);
                } else {
                    const float2 ho = *reinterpret_cast<const float2*>(h_old + idx);
                    const float2 xe = *reinterpret_cast<const float2*>(xemb + idx);
                    float2 o;
                    o.x = 0.5f * ho.x + 0.5f * (v0 + xe.x);
                    o.y = 0.5f * ho.y + 0.5f * (v1 + xe.y);
                    *reinterpret_cast<float2*>(outF + idx) = o;
                }
            }
        }
    }
}

// ---------------- fp32 SGEMM (embed / head) ---------------------------------
#define EPI_BIAS        0
#define EPI_BIAS_COPY2  1

template <int EPI>
__global__ __launch_bounds__(256, 2)
void sgemm_nt(int M, int N, int K,
              const float* __restrict__ A, const float* __restrict__ Bm,
              const float* __restrict__ bias, float* __restrict__ C,
              float* __restrict__ C2)
{
    __shared__ __align__(16) float As[2][8][128];
    __shared__ __align__(16) float Bs[2][8][128];
    const int tid = threadIdx.x;
    const int m0 = blockIdx.y * 128, n0 = blockIdx.x * 128;
    const int lr = tid >> 1, lk = (tid & 1) * 4;
    const int arow = m0 + lr, brow = n0 + lr;
    const bool bvalid = (brow < N);
    const int cm = (tid >> 4) * 8, cn = (tid & 15) * 8;

    float acc[8][8];
    #pragma unroll
    for (int i = 0; i < 8; ++i)
        #pragma unroll
        for (int j = 0; j < 8; ++j) acc[i][j] = 0.f;

    const int nk = K >> 3;
    float4 a4 = *reinterpret_cast<const float4*>(A + (size_t)arow * K + lk);
    float4 b4 = make_float4(0.f, 0.f, 0.f, 0.f);
    if (bvalid) b4 = *reinterpret_cast<const float4*>(Bm + (size_t)brow * K + lk);
    As[0][lk+0][lr]=a4.x; As[0][lk+1][lr]=a4.y; As[0][lk+2][lr]=a4.z; As[0][lk+3][lr]=a4.w;
    Bs[0][lk+0][lr]=b4.x; Bs[0][lk+1][lr]=b4.y; Bs[0][lk+2][lr]=b4.z; Bs[0][lk+3][lr]=b4.w;
    __syncthreads();

    int buf = 0;
    for (int kt = 0; kt < nk; ++kt) {
        const bool nx = (kt + 1) < nk;
        if (nx) {
            const int ko = (kt + 1) * 8 + lk;
            a4 = *reinterpret_cast<const float4*>(A + (size_t)arow * K + ko);
            b4 = bvalid ? *reinterpret_cast<const float4*>(Bm + (size_t)brow * K + ko)
                        : make_float4(0.f, 0.f, 0.f, 0.f);
        }
        #pragma unroll
        for (int k = 0; k < 8; ++k) {
            float af[8], bf[8];
            *reinterpret_cast<float4*>(af)   = *reinterpret_cast<const float4*>(&As[buf][k][cm]);
            *reinterpret_cast<float4*>(af+4) = *reinterpret_cast<const float4*>(&As[buf][k][cm+4]);
            *reinterpret_cast<float4*>(bf)   = *reinterpret_cast<const float4*>(&Bs[buf][k][cn]);
            *reinterpret_cast<float4*>(bf+4) = *reinterpret_cast<const float4*>(&Bs[buf][k][cn+4]);
            #pragma unroll
            for (int i = 0; i < 8; ++i)
                #pragma unroll
                for (int j = 0; j < 8; ++j) acc[i][j] = fmaf(af[i], bf[j], acc[i][j]);
        }
        if (nx) {
            const int nb = buf ^ 1;
            As[nb][lk+0][lr]=a4.x; As[nb][lk+1][lr]=a4.y; As[nb][lk+2][lr]=a4.z; As[nb][lk+3][lr]=a4.w;
            Bs[nb][lk+0][lr]=b4.x; Bs[nb][lk+1][lr]=b4.y; Bs[nb][lk+2][lr]=b4.z; Bs[nb][lk+3][lr]=b4.w;
            __syncthreads();
            buf = nb;
        }
    }
    #pragma unroll
    for (int i = 0; i < 8; ++i) {
        const int m = m0 + cm + i;
        #pragma unroll
        for (int j = 0; j < 8; ++j) {
            const int n = n0 + cn + j;
            if (n < N) {
                const float v = acc[i][j] + bias[n];
                const size_t idx = (size_t)m * N + n;
                C[idx] = v;
                if (EPI == EPI_BIAS_COPY2) C2[idx] = v;
            }
        }
    }
}

// ---------------- LayerNorm -> (hi, lo) fp16 --------------------------------
__device__ __forceinline__ float block_sum_256(float v, float* sh)
{
    #pragma unroll
    for (int o = 16; o > 0; o >>= 1) v += __shfl_xor_sync(0xffffffffu, v, o);
    const int w = threadIdx.x >> 5;
    __syncthreads();
    if ((threadIdx.x & 31) == 0) sh[w] = v;
    __syncthreads();
    float r = 0.f;
    if (threadIdx.x < 8) r = sh[threadIdx.x];
    if (threadIdx.x < 32) {
        #pragma unroll
        for (int o = 4; o > 0; o >>= 1) r += __shfl_xor_sync(0xffffffffu, r, o);
        if (threadIdx.x == 0) sh[0] = r;
    }
    __syncthreads();
    return sh[0];
}

__global__ void layernorm_split_kernel(const float* __restrict__ h,
                                       const float* __restrict__ w,
                                       const float* __restrict__ b,
                                       fp16* __restrict__ ohi, fp16* __restrict__ olo)
{
    __shared__ float sh[8];
    const int row = blockIdx.x, tid = threadIdx.x;
    const float4 v = reinterpret_cast<const float4*>(h + (size_t)row * HDIM)[tid];
    float s = v.x + v.y + v.z + v.w;
    const float mean = block_sum_256(s, sh) * (1.f / HDIM);
    const float dx=v.x-mean, dy=v.y-mean, dz=v.z-mean, dw=v.w-mean;
    float sq = dx*dx + dy*dy + dz*dz + dw*dw;
    const float var = block_sum_256(sq, sh) * (1.f / HDIM);
    const float rstd = rsqrtf(var + LN_EPS);
    const float4 w4 = reinterpret_cast<const float4*>(w)[tid];
    const float4 b4 = reinterpret_cast<const float4*>(b)[tid];
    float o[4];
    o[0]=dx*rstd*w4.x+b4.x; o[1]=dy*rstd*w4.y+b4.y;
    o[2]=dz*rstd*w4.z+b4.z; o[3]=dw*rstd*w4.w+b4.w;
    fp16 hi[4], lo[4];
    #pragma unroll
    for (int k = 0; k < 4; ++k) {
        hi[k] = __float2half(o[k]);
        lo[k] = __float2half(o[k] - __half2float(hi[k]));
    }
    const size_t idx = (size_t)row * HDIM + tid * 4;
    uint2 wh; wh.x = h2u(hi[0], hi[1]); wh.y = h2u(hi[2], hi[3]);
    uint2 wl; wl.x = h2u(lo[0], lo[1]); wl.y = h2u(lo[2], lo[3]);
    *reinterpret_cast<uint2*>(ohi + idx) = wh;
    *reinterpret_cast<uint2*>(olo + idx) = wl;
}

// ---------------- fp32 -> fp16 convert (weights) ----------------------------
__global__ void tofp16_kernel(const float* __restrict__ src,
                              fp16* __restrict__ dst, int n)
{
    for (int i = 4 * (blockIdx.x * blockDim.x + threadIdx.x); i < n;
         i += 4 * gridDim.x * blockDim.x) {
        const float4 v = *reinterpret_cast<const float4*>(src + i);
        uint2 o;
        o.x = h2u(__float2half(v.x), __float2half(v.y));
        o.y = h2u(__float2half(v.z), __float2half(v.w));
        *reinterpret_cast<uint2*>(dst + i) = o;
    }
}

// ---------------- launch -----------------------------------------------------
extern "C" void kernel_launch(void* const* d_in, const int* in_sizes, int n_in,
                              void* d_out, int out_size)
{
    const float* x       = (const float*)d_in[0];
    const float* embed_w = (const float*)d_in[1];
    const float* embed_b = (const float*)d_in[2];
    const float* W1_w    = (const float*)d_in[3];
    const float* W1_b    = (const float*)d_in[4];
    const float* W2_w    = (const float*)d_in[5];
    const float* W2_b    = (const float*)d_in[6];
    const float* norm_w  = (const float*)d_in[7];
    const float* norm_b  = (const float*)d_in[8];
    const float* head_w  = (const float*)d_in[9];
    const float* head_b  = (const float*)d_in[10];

    float *p_xemb, *p_h;
    fp16 *p_hn_hi, *p_hn_lo, *p_hid_hi, *p_hid_lo, *p_w1, *p_w2;
    cudaGetSymbolAddress((void**)&p_xemb,   g_xemb);
    cudaGetSymbolAddress((void**)&p_h,      g_h);
    cudaGetSymbolAddress((void**)&p_hn_hi,  g_hn_hi);
    cudaGetSymbolAddress((void**)&p_hn_lo,  g_hn_lo);
    cudaGetSymbolAddress((void**)&p_hid_hi, g_hid_hi);
    cudaGetSymbolAddress((void**)&p_hid_lo, g_hid_lo);
    cudaGetSymbolAddress((void**)&p_w1,     g_w1);
    cudaGetSymbolAddress((void**)&p_w2,     g_w2);

    float* out = (float*)d_out;

    cudaFuncSetAttribute((const void*)hmma_gemm<HDIM,   FFNDIM, TCG_EPI_TANH>,
                         cudaFuncAttributeMaxDynamicSharedMemorySize, SMEM_MMA);
    cudaFuncSetAttribute((const void*)hmma_gemm<FFNDIM, HDIM,   TCG_EPI_STEP>,
                         cudaFuncAttributeMaxDynamicSharedMemorySize, SMEM_MMA);

    // weight conversion to fp16
    tofp16_kernel<<<512, 256>>>(W1_w, p_w1, FFNDIM * HDIM);
    tofp16_kernel<<<512, 256>>>(W2_w, p_w2, HDIM * FFNDIM);

    // x_emb = x @ embed_w^T + embed_b ; h0 = x_emb
    sgemm_nt<EPI_BIAS_COPY2><<<dim3(HDIM / 128, BROWS / 128), 256>>>(
        BROWS, HDIM, DIN, x, embed_w, embed_b, p_xemb, p_h);

    for (int s = 0; s < NSTEPS; ++s) {
        layernorm_split_kernel<<<BROWS, 256>>>(p_h, norm_w, norm_b, p_hn_hi, p_hn_lo);

        // hidden = tanh(hnorm @ W1^T + b1) -> (hi, lo) fp16
        hmma_gemm<HDIM, FFNDIM, TCG_EPI_TANH>
            <<<dim3(FFNDIM / 128, BROWS / 128), 256, SMEM_MMA>>>(
            p_hn_hi, p_hn_lo, p_w1, W1_b,
            p_hid_hi, p_hid_lo, nullptr, nullptr, nullptr);

        // h = 0.5*h + 0.5*(hidden @ W2^T + b2 + xemb)
        hmma_gemm<FFNDIM, HDIM, TCG_EPI_STEP>
            <<<dim3(HDIM / 128, BROWS / 128), 256, SMEM_MMA>>>(
            p_hid_hi, p_hid_lo, p_w2, W2_b,
            nullptr, nullptr, p_h, p_h, p_xemb);
    }

    // out = h @ head_w^T + head_b
    sgemm_nt<EPI_BIAS><<<dim3((DOUT + 127) / 128, BROWS / 128), 256>>>(
        BROWS, DOUT, HDIM, p_h, head_w, head_b, out, nullptr);
}

// round 16
// speedup vs baseline: 2.8538x; 1.8350x over previous
#include <cuda_runtime.h>
#include <cuda_fp16.h>
#include <math.h>
#include <stdint.h>

#define BROWS  4096
#define HDIM   1024
#define FFNDIM 4096
#define DIN    784
#define DOUT   1000
#define NSTEPS 30
#define LN_EPS 1e-5f

typedef __half fp16;

// ---------------- scratch ---------------------------------------------------
__device__ __align__(256) float g_xemb[(size_t)BROWS * HDIM];
__device__ __align__(256) float g_h   [(size_t)BROWS * HDIM];
__device__ __align__(256) fp16  g_hn  [(size_t)BROWS * HDIM];
__device__ __align__(256) fp16  g_hid [(size_t)BROWS * FFNDIM];
__device__ __align__(256) fp16  g_w1[(size_t)FFNDIM * HDIM];
__device__ __align__(256) fp16  g_w2[(size_t)HDIM * FFNDIM];

// ---------------- helpers ---------------------------------------------------
__device__ __forceinline__ uint32_t smem_u32(const void* p) {
    uint32_t a;
    asm("{ .reg .u64 t; cvta.to.shared.u64 t, %1; cvt.u32.u64 %0, t; }" : "=r"(a) : "l"(p));
    return a;
}
static __device__ __forceinline__ uint32_t swz128(uint32_t off) {
    return off ^ ((off >> 3) & 0x70u);
}
__device__ __forceinline__ uint32_t h2u(fp16 a, fp16 b) {
    return (uint32_t)__half_as_ushort(a) | ((uint32_t)__half_as_ushort(b) << 16);
}

#define CP_ASYNC16(saddr, gptr) \
    asm volatile("cp.async.cg.shared.global [%0], [%1], 16;" :: "r"(saddr), "l"(gptr) : "memory")
#define CP_COMMIT() asm volatile("cp.async.commit_group;" ::: "memory")
#define CP_WAIT1()  asm volatile("cp.async.wait_group 1;" ::: "memory")

#define LDSM_X4(r0, r1, r2, r3, addr) \
    asm volatile("ldmatrix.sync.aligned.m8n8.x4.shared.b16 {%0,%1,%2,%3}, [%4];" \
        : "=r"(r0), "=r"(r1), "=r"(r2), "=r"(r3) : "r"(addr))

#define MMA_FP16(d, a, b0, b1) \
    asm volatile("mma.sync.aligned.m16n8k16.row.col.f32.f16.f16.f32 " \
        "{%0,%1,%2,%3}, {%4,%5,%6,%7}, {%8,%9}, {%0,%1,%2,%3};" \
        : "+f"((d)[0]), "+f"((d)[1]), "+f"((d)[2]), "+f"((d)[3]) \
        : "r"((a)[0]), "r"((a)[1]), "r"((a)[2]), "r"((a)[3]), "r"(b0), "r"(b1))

// ---------------- fp16 HMMA GEMM ---------------------------------------------
// D[M,N] = A[M,K] @ B[N,K]^T, plain fp16 operands, fp32 accumulate.
// CTA tile 128x128, 256 threads (8 warps = 2m x 4n, warp tile 64x32).
// BK=64, 3-stage cp.async pipeline, 96KB smem -> 2 CTAs/SM.  (R12 structure)
#define TCG_EPI_TANH 0
#define TCG_EPI_STEP 1

#define NSTG 3
#define STAGE_A_BYTES 16384            // 128 rows x 128B
#define STAGE_BYTES   32768            // A + B
#define SMEM_MMA (NSTG * STAGE_BYTES)  // 96 KB

template <int KTOT, int NTOT, int EPI>
__global__ __launch_bounds__(256, 2)
void hmma_gemm(const fp16* __restrict__ A,
               const fp16* __restrict__ B,
               const float* __restrict__ bias,
               fp16*  __restrict__ outH,
               float* __restrict__ outF,
               const float* __restrict__ h_old, const float* __restrict__ xemb)
{
    constexpr int KC_TOTAL = KTOT / 64;

    extern __shared__ __align__(1024) char smem[];
    const uint32_t sb = smem_u32(smem);

    const int tid  = threadIdx.x;
    const int wid  = tid >> 5;
    const int lane = tid & 31;
    const int m0 = blockIdx.y * 128;
    const int n0 = blockIdx.x * 128;
    const int wm = (wid >> 2) * 64;    // 0 / 64
    const int wn = (wid & 3) * 32;     // 0..96

    float acc[4][4][4];
    #pragma unroll
    for (int i = 0; i < 4; ++i)
        #pragma unroll
        for (int j = 0; j < 4; ++j)
            #pragma unroll
            for (int k = 0; k < 4; ++k) acc[i][j][k] = 0.f;

    auto load_stage = [&](int slot, int c) {
        const int ko = c * 64;
        const uint32_t ab = sb + slot * STAGE_BYTES;
        const uint32_t bb = ab + STAGE_A_BYTES;
        #pragma unroll
        for (int i = 0; i < 4; ++i) {
            const int u = tid + i * 256, r = u >> 3, c8 = u & 7;
            CP_ASYNC16(ab + swz128(r * 128 + c8 * 16),
                       A + (size_t)(m0 + r) * KTOT + ko + c8 * 8);
        }
        #pragma unroll
        for (int i = 0; i < 4; ++i) {
            const int u = tid + i * 256, r = u >> 3, c8 = u & 7;
            CP_ASYNC16(bb + swz128(r * 128 + c8 * 16),
                       B + (size_t)(n0 + r) * KTOT + ko + c8 * 8);
        }
    };

    // prologue: fill 2 stages
    load_stage(0, 0); CP_COMMIT();
    load_stage(1, 1); CP_COMMIT();

    const int lrow  = lane & 15;
    const int lhalf = lane >> 4;

    int rs = 0;
    for (int c = 0; c < KC_TOTAL; ++c) {
        CP_WAIT1();
        __syncthreads();

        const uint32_t ab = sb + rs * STAGE_BYTES;
        const uint32_t bb = ab + STAGE_A_BYTES;

        #pragma unroll
        for (int kk = 0; kk < 64; kk += 16) {
            uint32_t afr[4][4];
            #pragma unroll
            for (int mi = 0; mi < 4; ++mi) {
                const uint32_t ad = ab + swz128((wm + mi * 16 + lrow) * 128 + kk * 2 + lhalf * 16);
                LDSM_X4(afr[mi][0], afr[mi][1], afr[mi][2], afr[mi][3], ad);
            }
            uint32_t bfr[2][4];
            #pragma unroll
            for (int g = 0; g < 2; ++g) {
                const uint32_t bd = bb + swz128((wn + g * 16 + lrow) * 128 + kk * 2 + lhalf * 16);
                LDSM_X4(bfr[g][0], bfr[g][1], bfr[g][2], bfr[g][3], bd);
            }
            #pragma unroll
            for (int mi = 0; mi < 4; ++mi) {
                #pragma unroll
                for (int nj = 0; nj < 4; ++nj) {
                    const int g = nj >> 1, h = nj & 1;
                    MMA_FP16(acc[mi][nj], afr[mi], bfr[g][h ? 1 : 0], bfr[g][h ? 3 : 2]);
                }
            }
        }

        if (c + 2 < KC_TOTAL) {
            int ws = rs + 2; if (ws >= NSTG) ws -= NSTG;
            load_stage(ws, c + 2);
        }
        CP_COMMIT();
        __syncthreads();
        if (++rs == NSTG) rs = 0;
    }

    // ---------------- epilogue ----------------------------------------------
    const int erow = lane >> 2;          // 0..7
    const int ecol = (lane & 3) * 2;     // 0,2,4,6

    #pragma unroll
    for (int mi = 0; mi < 4; ++mi) {
        #pragma unroll
        for (int nj = 0; nj < 4; ++nj) {
            const int n = n0 + wn + nj * 8 + ecol;
            const float2 b2 = *reinterpret_cast<const float2*>(bias + n);
            #pragma unroll
            for (int half = 0; half < 2; ++half) {
                const int m = m0 + wm + mi * 16 + erow + half * 8;
                const float v0 = acc[mi][nj][half * 2 + 0] + b2.x;
                const float v1 = acc[mi][nj][half * 2 + 1] + b2.y;
                const size_t idx = (size_t)m * NTOT + n;
                if (EPI == TCG_EPI_TANH) {
                    const float t0 = tanhf(v0), t1 = tanhf(v1);
                    *reinterpret_cast<uint32_t*>(outH + idx) =
                        h2u(__float2half(t0), __float2half(t1));
                } else {
                    const float2 ho = *reinterpret_cast<const float2*>(h_old + idx);
                    const float2 xe = *reinterpret_cast<const float2*>(xemb + idx);
                    float2 o;
                    o.x = 0.5f * ho.x + 0.5f * (v0 + xe.x);
                    o.y = 0.5f * ho.y + 0.5f * (v1 + xe.y);
                    *reinterpret_cast<float2*>(outF + idx) = o;
                }
            }
        }
    }
}

// ---------------- fp32 SGEMM (embed / head) ---------------------------------
#define EPI_BIAS        0
#define EPI_BIAS_COPY2  1

template <int EPI>
__global__ __launch_bounds__(256, 2)
void sgemm_nt(int M, int N, int K,
              const float* __restrict__ A, const float* __restrict__ Bm,
              const float* __restrict__ bias, float* __restrict__ C,
              float* __restrict__ C2)
{
    __shared__ __align__(16) float As[2][8][128];
    __shared__ __align__(16) float Bs[2][8][128];
    const int tid = threadIdx.x;
    const int m0 = blockIdx.y * 128, n0 = blockIdx.x * 128;
    const int lr = tid >> 1, lk = (tid & 1) * 4;
    const int arow = m0 + lr, brow = n0 + lr;
    const bool bvalid = (brow < N);
    const int cm = (tid >> 4) * 8, cn = (tid & 15) * 8;

    float acc[8][8];
    #pragma unroll
    for (int i = 0; i < 8; ++i)
        #pragma unroll
        for (int j = 0; j < 8; ++j) acc[i][j] = 0.f;

    const int nk = K >> 3;
    float4 a4 = *reinterpret_cast<const float4*>(A + (size_t)arow * K + lk);
    float4 b4 = make_float4(0.f, 0.f, 0.f, 0.f);
    if (bvalid) b4 = *reinterpret_cast<const float4*>(Bm + (size_t)brow * K + lk);
    As[0][lk+0][lr]=a4.x; As[0][lk+1][lr]=a4.y; As[0][lk+2][lr]=a4.z; As[0][lk+3][lr]=a4.w;
    Bs[0][lk+0][lr]=b4.x; Bs[0][lk+1][lr]=b4.y; Bs[0][lk+2][lr]=b4.z; Bs[0][lk+3][lr]=b4.w;
    __syncthreads();

    int buf = 0;
    for (int kt = 0; kt < nk; ++kt) {
        const bool nx = (kt + 1) < nk;
        if (nx) {
            const int ko = (kt + 1) * 8 + lk;
            a4 = *reinterpret_cast<const float4*>(A + (size_t)arow * K + ko);
            b4 = bvalid ? *reinterpret_cast<const float4*>(Bm + (size_t)brow * K + ko)
                        : make_float4(0.f, 0.f, 0.f, 0.f);
        }
        #pragma unroll
        for (int k = 0; k < 8; ++k) {
            float af[8], bf[8];
            *reinterpret_cast<float4*>(af)   = *reinterpret_cast<const float4*>(&As[buf][k][cm]);
            *reinterpret_cast<float4*>(af+4) = *reinterpret_cast<const float4*>(&As[buf][k][cm+4]);
            *reinterpret_cast<float4*>(bf)   = *reinterpret_cast<const float4*>(&Bs[buf][k][cn]);
            *reinterpret_cast<float4*>(bf+4) = *reinterpret_cast<const float4*>(&Bs[buf][k][cn+4]);
            #pragma unroll
            for (int i = 0; i < 8; ++i)
                #pragma unroll
                for (int j = 0; j < 8; ++j) acc[i][j] = fmaf(af[i], bf[j], acc[i][j]);
        }
        if (nx) {
            const int nb = buf ^ 1;
            As[nb][lk+0][lr]=a4.x; As[nb][lk+1][lr]=a4.y; As[nb][lk+2][lr]=a4.z; As[nb][lk+3][lr]=a4.w;
            Bs[nb][lk+0][lr]=b4.x; Bs[nb][lk+1][lr]=b4.y; Bs[nb][lk+2][lr]=b4.z; Bs[nb][lk+3][lr]=b4.w;
            __syncthreads();
            buf = nb;
        }
    }
    #pragma unroll
    for (int i = 0; i < 8; ++i) {
        const int m = m0 + cm + i;
        #pragma unroll
        for (int j = 0; j < 8; ++j) {
            const int n = n0 + cn + j;
            if (n < N) {
                const float v = acc[i][j] + bias[n];
                const size_t idx = (size_t)m * N + n;
                C[idx] = v;
                if (EPI == EPI_BIAS_COPY2) C2[idx] = v;
            }
        }
    }
}

// ---------------- LayerNorm -> fp16 -----------------------------------------
__device__ __forceinline__ float block_sum_256(float v, float* sh)
{
    #pragma unroll
    for (int o = 16; o > 0; o >>= 1) v += __shfl_xor_sync(0xffffffffu, v, o);
    const int w = threadIdx.x >> 5;
    __syncthreads();
    if ((threadIdx.x & 31) == 0) sh[w] = v;
    __syncthreads();
    float r = 0.f;
    if (threadIdx.x < 8) r = sh[threadIdx.x];
    if (threadIdx.x < 32) {
        #pragma unroll
        for (int o = 4; o > 0; o >>= 1) r += __shfl_xor_sync(0xffffffffu, r, o);
        if (threadIdx.x == 0) sh[0] = r;
    }
    __syncthreads();
    return sh[0];
}

__global__ void layernorm_fp16_kernel(const float* __restrict__ h,
                                      const float* __restrict__ w,
                                      const float* __restrict__ b,
                                      fp16* __restrict__ oh)
{
    __shared__ float sh[8];
    const int row = blockIdx.x, tid = threadIdx.x;
    const float4 v = reinterpret_cast<const float4*>(h + (size_t)row * HDIM)[tid];
    float s = v.x + v.y + v.z + v.w;
    const float mean = block_sum_256(s, sh) * (1.f / HDIM);
    const float dx=v.x-mean, dy=v.y-mean, dz=v.z-mean, dw=v.w-mean;
    float sq = dx*dx + dy*dy + dz*dz + dw*dw;
    const float var = block_sum_256(sq, sh) * (1.f / HDIM);
    const float rstd = rsqrtf(var + LN_EPS);
    const float4 w4 = reinterpret_cast<const float4*>(w)[tid];
    const float4 b4 = reinterpret_cast<const float4*>(b)[tid];
    float o[4];
    o[0]=dx*rstd*w4.x+b4.x; o[1]=dy*rstd*w4.y+b4.y;
    o[2]=dz*rstd*w4.z+b4.z; o[3]=dw*rstd*w4.w+b4.w;
    const size_t idx = (size_t)row * HDIM + tid * 4;
    uint2 wh;
    wh.x = h2u(__float2half(o[0]), __float2half(o[1]));
    wh.y = h2u(__float2half(o[2]), __float2half(o[3]));
    *reinterpret_cast<uint2*>(oh + idx) = wh;
}

// ---------------- fp32 -> fp16 convert (weights) ----------------------------
__global__ void tofp16_kernel(const float* __restrict__ src,
                              fp16* __restrict__ dst, int n)
{
    for (int i = 4 * (blockIdx.x * blockDim.x + threadIdx.x); i < n;
         i += 4 * gridDim.x * blockDim.x) {
        const float4 v = *reinterpret_cast<const float4*>(src + i);
        uint2 o;
        o.x = h2u(__float2half(v.x), __float2half(v.y));
        o.y = h2u(__float2half(v.z), __float2half(v.w));
        *reinterpret_cast<uint2*>(dst + i) = o;
    }
}

// ---------------- launch -----------------------------------------------------
extern "C" void kernel_launch(void* const* d_in, const int* in_sizes, int n_in,
                              void* d_out, int out_size)
{
    const float* x       = (const float*)d_in[0];
    const float* embed_w = (const float*)d_in[1];
    const float* embed_b = (const float*)d_in[2];
    const float* W1_w    = (const float*)d_in[3];
    const float* W1_b    = (const float*)d_in[4];
    const float* W2_w    = (const float*)d_in[5];
    const float* W2_b    = (const float*)d_in[6];
    const float* norm_w  = (const float*)d_in[7];
    const float* norm_b  = (const float*)d_in[8];
    const float* head_w  = (const float*)d_in[9];
    const float* head_b  = (const float*)d_in[10];

    float *p_xemb, *p_h;
    fp16 *p_hn, *p_hid, *p_w1, *p_w2;
    cudaGetSymbolAddress((void**)&p_xemb, g_xemb);
    cudaGetSymbolAddress((void**)&p_h,    g_h);
    cudaGetSymbolAddress((void**)&p_hn,   g_hn);
    cudaGetSymbolAddress((void**)&p_hid,  g_hid);
    cudaGetSymbolAddress((void**)&p_w1,   g_w1);
    cudaGetSymbolAddress((void**)&p_w2,   g_w2);

    float* out = (float*)d_out;

    cudaFuncSetAttribute((const void*)hmma_gemm<HDIM,   FFNDIM, TCG_EPI_TANH>,
                         cudaFuncAttributeMaxDynamicSharedMemorySize, SMEM_MMA);
    cudaFuncSetAttribute((const void*)hmma_gemm<FFNDIM, HDIM,   TCG_EPI_STEP>,
                         cudaFuncAttributeMaxDynamicSharedMemorySize, SMEM_MMA);

    // weight conversion to fp16
    tofp16_kernel<<<512, 256>>>(W1_w, p_w1, FFNDIM * HDIM);
    tofp16_kernel<<<512, 256>>>(W2_w, p_w2, HDIM * FFNDIM);

    // x_emb = x @ embed_w^T + embed_b ; h0 = x_emb
    sgemm_nt<EPI_BIAS_COPY2><<<dim3(HDIM / 128, BROWS / 128), 256>>>(
        BROWS, HDIM, DIN, x, embed_w, embed_b, p_xemb, p_h);

    for (int s = 0; s < NSTEPS; ++s) {
        layernorm_fp16_kernel<<<BROWS, 256>>>(p_h, norm_w, norm_b, p_hn);

        // hidden = tanh(hnorm @ W1^T + b1) -> fp16
        hmma_gemm<HDIM, FFNDIM, TCG_EPI_TANH>
            <<<dim3(FFNDIM / 128, BROWS / 128), 256, SMEM_MMA>>>(
            p_hn, p_w1, W1_b, p_hid, nullptr, nullptr, nullptr);

        // h = 0.5*h + 0.5*(hidden @ W2^T + b2 + xemb)
        hmma_gemm<FFNDIM, HDIM, TCG_EPI_STEP>
            <<<dim3(HDIM / 128, BROWS / 128), 256, SMEM_MMA>>>(
            p_hid, p_w2, W2_b, nullptr, p_h, p_h, p_xemb);
    }

    // out = h @ head_w^T + head_b
    sgemm_nt<EPI_BIAS><<<dim3((DOUT + 127) / 128, BROWS / 128), 256>>>(
        BROWS, DOUT, HDIM, p_h, head_w, head_b, out, nullptr);
}